// round 10
// baseline (speedup 1.0000x reference)
#include <cuda_runtime.h>
#include <math.h>

#define L      2304
#define DM     128
#define DI     256
#define DS     16
#define DTR    8
#define NPROJ  40   // DTR + 2*DS
#define NDEPTH 8
#define CHK    16
#define NC     (L/CHK)   // 144
#define NSEQ   (DI*DS)   // 4096
#define SEQT   32
#define NBLK   144
#define NTHR   256

// ---------------- scratch (device globals; no allocations) ----------------
__device__ float g_seq[L*DM];
__device__ float g_xz [L*2*DI];
__device__ float g_xc [L*DI];
__device__ float g_dbl[L*NPROJ];
__device__ float g_dt [L*DI];
__device__ float g_chA[NC*NSEQ];   // [chunk][s*DI + d]
__device__ float g_chB[NC*NSEQ];
__device__ float g_h0 [NC*NSEQ];
__device__ unsigned g_count;
__device__ unsigned g_gen;

// ---------------- shared-memory union (dynamic smem) ----------------
struct SmemT { float t[32][33]; };
struct SmemG { float As[16][68]; float Bs[16][128]; };
struct SmemM { float xc[CHK*257]; float Wx[128*48]; float dbl[CHK*NPROJ]; };
struct SmemS { float A[NC][SEQT+1]; float B[NC][SEQT+1]; };
struct SmemO { float y[CHK*DI]; float Wo[32*DM]; float Bs[CHK][DS]; float Cs[CHK][DS]; };
union SmemU { SmemT t; SmemG g; SmemM m; SmemS s; SmemO o; };

// ---------------- grid barrier (all NBLK blocks resident) ----------------
__device__ __forceinline__ void gsync() {
    __syncthreads();
    if (threadIdx.x == 0) {
        __threadfence();
        unsigned gen = *(volatile unsigned*)&g_gen;
        unsigned arr = atomicAdd(&g_count, 1u);
        if (arr == NBLK - 1) {
            g_count = 0;
            __threadfence();
            *(volatile unsigned*)&g_gen = gen + 1;
        } else {
            while (*(volatile unsigned*)&g_gen == gen) __nanosleep(32);
        }
        __threadfence();
    }
    __syncthreads();
}

// ================= phase: transpose in/out (2 tiles per block) =================
__device__ __noinline__ void ph_transpose_in(const float* __restrict__ x) {
    extern __shared__ char smraw[];
    SmemT& st = reinterpret_cast<SmemU*>(smraw)->t;
    int bid = blockIdx.x, wrp = threadIdx.x >> 5, lane = threadIdx.x & 31;
    for (int tile = bid; tile < (L/32)*(DM/32); tile += NBLK) {
        int l0 = (tile % (L/32)) * 32, c0 = (tile / (L/32)) * 32;
        __syncthreads();
        #pragma unroll
        for (int i = wrp; i < 32; i += 8)
            st.t[i][lane] = x[(c0 + i) * L + l0 + lane];
        __syncthreads();
        #pragma unroll
        for (int i = wrp; i < 32; i += 8)
            g_seq[(l0 + i) * DM + c0 + lane] = st.t[lane][i];
    }
}

__device__ __noinline__ void ph_transpose_out(float* __restrict__ out) {
    extern __shared__ char smraw[];
    SmemT& st = reinterpret_cast<SmemU*>(smraw)->t;
    int bid = blockIdx.x, wrp = threadIdx.x >> 5, lane = threadIdx.x & 31;
    for (int tile = bid; tile < (L/32)*(DM/32); tile += NBLK) {
        int l0 = (tile % (L/32)) * 32, c0 = (tile / (L/32)) * 32;
        __syncthreads();
        #pragma unroll
        for (int i = wrp; i < 32; i += 8)
            st.t[i][lane] = g_seq[(l0 + i) * DM + c0 + lane];
        __syncthreads();
        #pragma unroll
        for (int i = wrp; i < 32; i += 8)
            out[(c0 + i) * L + l0 + lane] = st.t[lane][i];
    }
}

// ================= phase: in-proj GEMM, one 64x128 tile per block =================
__device__ __noinline__ void ph_gemm_in(const float* __restrict__ Wi) {
    extern __shared__ char smraw[];
    SmemG& sg = reinterpret_cast<SmemU*>(smraw)->g;
    int t = threadIdx.x, bid = blockIdx.x;
    int row0 = (bid >> 2) * 64, col0 = (bid & 3) * 128;
    int tr = t >> 4, tc = t & 15;   // 4 rows x 8 cols per thread
    float acc[4][8] = {};
    for (int k0 = 0; k0 < DM; k0 += 16) {
        {   // As: 64m x 16k
            int m = t >> 2, kq = t & 3;
            float4 v = *(const float4*)&g_seq[(row0 + m) * DM + k0 + kq * 4];
            sg.As[kq*4+0][m] = v.x; sg.As[kq*4+1][m] = v.y;
            sg.As[kq*4+2][m] = v.z; sg.As[kq*4+3][m] = v.w;
        }
        #pragma unroll
        for (int i = 0; i < 2; i++) {   // Bs: 16k x 128c
            int li = t + i * 256;
            int k = li >> 5, c4 = li & 31;
            *(float4*)&sg.Bs[k][c4 * 4] =
                *(const float4*)&Wi[(k0 + k) * 512 + col0 + c4 * 4];
        }
        __syncthreads();
        #pragma unroll
        for (int k = 0; k < 16; k++) {
            float a[4], b[8];
            *(float4*)&a[0] = *(float4*)&sg.As[k][tr * 4];
            *(float4*)&b[0] = *(float4*)&sg.Bs[k][tc * 8];
            *(float4*)&b[4] = *(float4*)&sg.Bs[k][tc * 8 + 4];
            #pragma unroll
            for (int i = 0; i < 4; i++)
                #pragma unroll
                for (int j = 0; j < 8; j++)
                    acc[i][j] += a[i] * b[j];
        }
        __syncthreads();
    }
    #pragma unroll
    for (int i = 0; i < 4; i++) {
        int r = row0 + tr * 4 + i;
        float4 v0 = {acc[i][0], acc[i][1], acc[i][2], acc[i][3]};
        float4 v1 = {acc[i][4], acc[i][5], acc[i][6], acc[i][7]};
        *(float4*)&g_xz[r * 512 + col0 + tc * 8]     = v0;
        *(float4*)&g_xz[r * 512 + col0 + tc * 8 + 4] = v1;
    }
}

// ================= phase: conv+SiLU -> xproj -> dt -> scan pass 1 =================
__device__ __noinline__ void ph_mid(const float* __restrict__ cw, const float* __restrict__ cb,
                                    const float* __restrict__ Wx, const float* __restrict__ Wd,
                                    const float* __restrict__ bd, const float* __restrict__ Al) {
    extern __shared__ char smraw[];
    SmemM& smm = reinterpret_cast<SmemU*>(smraw)->m;
    int t = threadIdx.x;
    int l0 = blockIdx.x * CHK;
    int d = t;
    float xcr[CHK], dtr[CHK];

    // conv + SiLU: batched loads
    {
        float v[CHK + 3];
        #pragma unroll
        for (int i = 0; i < CHK + 3; i++) {
            int l = l0 + i - 3;
            v[i] = (l >= 0) ? g_xz[l*512 + d] : 0.f;
        }
        float c0 = cw[d*4+0], c1 = cw[d*4+1], c2 = cw[d*4+2], c3 = cw[d*4+3];
        float bb = cb[d];
        #pragma unroll
        for (int r = 0; r < CHK; r++) {
            float acc = bb + v[r]*c0 + v[r+1]*c1 + v[r+2]*c2 + v[r+3]*c3;
            acc = acc / (1.f + __expf(-acc));
            xcr[r] = acc;
            smm.xc[r*257 + d] = acc;
            g_xc[(l0+r)*DI + d] = acc;
        }
    }

    // xproj: dbl[16,40] = xc[16,256] @ Wx[256,40]
    int row = t & 15, g = t >> 4;
    int c0i = g * 3;
    float a0 = 0.f, a1 = 0.f, a2 = 0.f;
    for (int p = 0; p < 2; p++) {
        __syncthreads();
        for (int i = t; i < 128 * NPROJ; i += 256) {
            int k = i / NPROJ, c = i % NPROJ;
            smm.Wx[k*48 + c] = Wx[(p*128 + k) * NPROJ + c];
        }
        __syncthreads();
        const float* xr = smm.xc + row*257 + p*128;
        #pragma unroll 4
        for (int k = 0; k < 128; k++) {
            float xv = xr[k];
            a0 += xv * smm.Wx[k*48 + c0i];
            a1 += xv * smm.Wx[k*48 + c0i + 1];
            a2 += xv * smm.Wx[k*48 + c0i + 2];
        }
    }
    if (c0i     < NPROJ) { smm.dbl[row*NPROJ + c0i]     = a0; g_dbl[(l0+row)*NPROJ + c0i]     = a0; }
    if (c0i + 1 < NPROJ) { smm.dbl[row*NPROJ + c0i + 1] = a1; g_dbl[(l0+row)*NPROJ + c0i + 1] = a1; }
    if (c0i + 2 < NPROJ) { smm.dbl[row*NPROJ + c0i + 2] = a2; g_dbl[(l0+row)*NPROJ + c0i + 2] = a2; }
    __syncthreads();

    // dt = softplus
    {
        float w[DTR];
        #pragma unroll
        for (int k = 0; k < DTR; k++) w[k] = Wd[k*DI + d];
        float bb = bd[d];
        #pragma unroll
        for (int r = 0; r < CHK; r++) {
            float acc = bb;
            #pragma unroll
            for (int k = 0; k < DTR; k++) acc += smm.dbl[r*NPROJ + k] * w[k];
            float sp = (acc > 20.f) ? acc : log1pf(__expf(acc));
            dtr[r] = sp;
            g_dt[(l0+r)*DI + d] = sp;
        }
    }

    // scan pass 1
    {
        float Arow[DS], a[DS], b[DS];
        #pragma unroll
        for (int s = 0; s < DS; s++) {
            Arow[s] = -__expf(Al[d*DS + s]);
            a[s] = 1.f; b[s] = 0.f;
        }
        #pragma unroll 4
        for (int r = 0; r < CHK; r++) {
            float dt = dtr[r], dtxc = dt * xcr[r];
            #pragma unroll
            for (int s = 0; s < DS; s++) {
                float dA = __expf(dt * Arow[s]);
                b[s] = dA * b[s] + dtxc * smm.dbl[r*NPROJ + DTR + s];
                a[s] *= dA;
            }
        }
        int base = blockIdx.x * NSEQ + d;
        #pragma unroll
        for (int s = 0; s < DS; s++) {
            g_chA[base + s*DI] = a[s];
            g_chB[base + s*DI] = b[s];
        }
    }
}

// ================= phase: chunk combine (batched + round-parallel KS) =================
__device__ __noinline__ void ph_scan2() {
    extern __shared__ char smraw[];
    SmemS& ss = reinterpret_cast<SmemU*>(smraw)->s;
    int bid = blockIdx.x;
    if (bid >= NSEQ / SEQT) return;
    int wrp = threadIdx.x >> 5, lane = threadIdx.x & 31;
    int seq0 = bid * SEQT;

    {   // batched register staging: 18 rows per warp
        float la[18], lb[18];
        #pragma unroll
        for (int i = 0; i < 18; i++) {
            int c = wrp + i * 8;
            la[i] = g_chA[c * NSEQ + seq0 + lane];
            lb[i] = g_chB[c * NSEQ + seq0 + lane];
        }
        #pragma unroll
        for (int i = 0; i < 18; i++) {
            int c = wrp + i * 8;
            ss.A[c][lane] = la[i];
            ss.B[c][lane] = lb[i];
        }
    }
    __syncthreads();
    #pragma unroll
    for (int q = 0; q < 4; q++) {
        int col = wrp * 4 + q;
        float ra[5], rb[5];
        #pragma unroll
        for (int k = 0; k < 5; k++) {
            int c = k * 32 + lane;
            if (c < NC) { ra[k] = ss.A[c][col]; rb[k] = ss.B[c][col]; }
            else        { ra[k] = 1.f;          rb[k] = 0.f; }
        }
        #pragma unroll
        for (int off = 1; off < 32; off <<= 1) {
            float pa[5], pb[5];
            #pragma unroll
            for (int k = 0; k < 5; k++) {
                pa[k] = __shfl_up_sync(0xffffffffu, ra[k], off);
                pb[k] = __shfl_up_sync(0xffffffffu, rb[k], off);
            }
            #pragma unroll
            for (int k = 0; k < 5; k++)
                if (lane >= off) { rb[k] = ra[k] * pb[k] + rb[k]; ra[k] *= pa[k]; }
        }
        float ea[5], eb[5];
        #pragma unroll
        for (int k = 0; k < 5; k++) {
            ea[k] = __shfl_up_sync(0xffffffffu, ra[k], 1);
            eb[k] = __shfl_up_sync(0xffffffffu, rb[k], 1);
            if (lane == 0) { ea[k] = 1.f; eb[k] = 0.f; }
        }
        float H = 0.f;
        #pragma unroll
        for (int k = 0; k < 5; k++) {
            int c = k * 32 + lane;
            float h0 = ea[k] * H + eb[k];
            if (c < NC) ss.A[c][col] = h0;
            float ta = __shfl_sync(0xffffffffu, ra[k], 31);
            float tb = __shfl_sync(0xffffffffu, rb[k], 31);
            H = ta * H + tb;
        }
    }
    __syncthreads();
    #pragma unroll
    for (int i = 0; i < 18; i++) {
        int c = wrp + i * 8;
        g_h0[c * NSEQ + seq0 + lane] = ss.A[c][lane];
    }
}

// ================= phase: scan pass 3 + gate -> out GEMM -> RMSNorm =================
__device__ __noinline__ void ph_out(const float* __restrict__ Al, const float* __restrict__ Dpp,
                                    const float* __restrict__ Wo, const float* __restrict__ rw) {
    extern __shared__ char smraw[];
    SmemO& so = reinterpret_cast<SmemU*>(smraw)->o;
    int t = threadIdx.x;
    int l0 = blockIdx.x * CHK;
    int wrp = t >> 5, lane = t & 31;

    {
        int r = t >> 4, s = t & 15;
        int base = (l0 + r) * NPROJ + DTR;
        so.Bs[r][s] = g_dbl[base + s];
        so.Cs[r][s] = g_dbl[base + DS + s];
    }
    // phase A: scan with init state, C-contract, D-skip, z-gate
    {
        int d = t;
        float dtv[CHK], xcv[CHK], zv[CHK], h[DS], Arow[DS];
        #pragma unroll
        for (int r = 0; r < CHK; r++) {
            int l = l0 + r;
            dtv[r] = g_dt[l*DI + d];
            xcv[r] = g_xc[l*DI + d];
            zv[r]  = g_xz[l*512 + DI + d];
        }
        int hb = blockIdx.x * NSEQ + d;
        #pragma unroll
        for (int s = 0; s < DS; s++) {
            Arow[s] = -__expf(Al[d*DS + s]);
            h[s] = g_h0[hb + s*DI];
        }
        float Dd = Dpp[d];
        __syncthreads();
        #pragma unroll 4
        for (int r = 0; r < CHK; r++) {
            float dt = dtv[r], xc = xcv[r];
            float dtxc = dt * xc;
            float y = Dd * xc;
            #pragma unroll
            for (int s = 0; s < DS; s++) {
                float dA = __expf(dt * Arow[s]);
                h[s] = dA * h[s] + dtxc * so.Bs[r][s];
                y += h[s] * so.Cs[r][s];
            }
            float z = zv[r];
            y *= z / (1.f + __expf(-z));
            so.y[r*DI + d] = y;
        }
    }
    // phase B: out[16,128] = y[16,256] @ Wo[256,128] + RMSNorm
    int r0 = 2*wrp, r1 = 2*wrp + 1;
    int cbl = lane * 4;
    float acc0[4] = {}, acc1[4] = {};
    for (int k0 = 0; k0 < DI; k0 += 32) {
        __syncthreads();
        #pragma unroll
        for (int i = 0; i < 4; i++) {
            int idx = t + 256*i;
            int kk = idx >> 5, c4 = idx & 31;
            ((float4*)so.Wo)[kk*32 + c4] = ((const float4*)(Wo + (k0+kk)*DM))[c4];
        }
        __syncthreads();
        #pragma unroll
        for (int kk = 0; kk < 32; kk += 4) {
            float4 y0 = *(const float4*)&so.y[r0*DI + k0 + kk];
            float4 y1 = *(const float4*)&so.y[r1*DI + k0 + kk];
            float ya0[4] = {y0.x, y0.y, y0.z, y0.w};
            float ya1[4] = {y1.x, y1.y, y1.z, y1.w};
            #pragma unroll
            for (int i = 0; i < 4; i++) {
                float4 wv = *(const float4*)&so.Wo[(kk+i)*DM + cbl];
                acc0[0] += ya0[i]*wv.x; acc0[1] += ya0[i]*wv.y;
                acc0[2] += ya0[i]*wv.z; acc0[3] += ya0[i]*wv.w;
                acc1[0] += ya1[i]*wv.x; acc1[1] += ya1[i]*wv.y;
                acc1[2] += ya1[i]*wv.z; acc1[3] += ya1[i]*wv.w;
            }
        }
    }
    float ss0 = acc0[0]*acc0[0] + acc0[1]*acc0[1] + acc0[2]*acc0[2] + acc0[3]*acc0[3];
    float ss1 = acc1[0]*acc1[0] + acc1[1]*acc1[1] + acc1[2]*acc1[2] + acc1[3]*acc1[3];
    #pragma unroll
    for (int o = 16; o > 0; o >>= 1) {
        ss0 += __shfl_xor_sync(0xffffffffu, ss0, o);
        ss1 += __shfl_xor_sync(0xffffffffu, ss1, o);
    }
    float sc0 = rsqrtf(ss0 * (1.f/DM) + 1e-5f);
    float sc1 = rsqrtf(ss1 * (1.f/DM) + 1e-5f);
    float4 rwv = *(const float4*)&rw[cbl];
    float4 o0, o1;
    o0.x = acc0[0]*sc0*rwv.x; o0.y = acc0[1]*sc0*rwv.y;
    o0.z = acc0[2]*sc0*rwv.z; o0.w = acc0[3]*sc0*rwv.w;
    o1.x = acc1[0]*sc1*rwv.x; o1.y = acc1[1]*sc1*rwv.y;
    o1.z = acc1[2]*sc1*rwv.z; o1.w = acc1[3]*sc1*rwv.w;
    *(float4*)&g_seq[(l0 + r0)*DM + cbl] = o0;
    *(float4*)&g_seq[(l0 + r1)*DM + cbl] = o1;
}

// ================= persistent kernel =================
__global__ void __launch_bounds__(NTHR) mamba_all_k(
    const float* __restrict__ x,
    const float* __restrict__ W_in,  const float* __restrict__ conv_w,
    const float* __restrict__ conv_b, const float* __restrict__ W_xp,
    const float* __restrict__ W_dt,  const float* __restrict__ b_dt,
    const float* __restrict__ A_log, const float* __restrict__ D_skip,
    const float* __restrict__ W_out, const float* __restrict__ rms_w,
    float* __restrict__ out)
{
    ph_transpose_in(x);
    gsync();
    for (int layer = 0; layer < NDEPTH; layer++) {
        ph_gemm_in(W_in + (size_t)layer * DM * 2 * DI);
        gsync();
        ph_mid(conv_w + (size_t)layer * DI * 4,
               conv_b + (size_t)layer * DI,
               W_xp   + (size_t)layer * DI * NPROJ,
               W_dt   + (size_t)layer * DTR * DI,
               b_dt   + (size_t)layer * DI,
               A_log  + (size_t)layer * DI * DS);
        gsync();
        ph_scan2();
        gsync();
        ph_out(A_log  + (size_t)layer * DI * DS,
               D_skip + (size_t)layer * DI,
               W_out  + (size_t)layer * DI * DM,
               rms_w  + (size_t)layer * DM);
        gsync();
    }
    ph_transpose_out(out);
}

// ---------------- launch ----------------
extern "C" void kernel_launch(void* const* d_in, const int* in_sizes, int n_in,
                              void* d_out, int out_size) {
    const float* x      = (const float*)d_in[0];
    const float* W_in   = (const float*)d_in[1];
    const float* conv_w = (const float*)d_in[2];
    const float* conv_b = (const float*)d_in[3];
    const float* W_xp   = (const float*)d_in[4];
    const float* W_dt   = (const float*)d_in[5];
    const float* b_dt   = (const float*)d_in[6];
    const float* A_log  = (const float*)d_in[7];
    const float* D_skip = (const float*)d_in[8];
    const float* W_out  = (const float*)d_in[9];
    const float* rms_w  = (const float*)d_in[10];
    float* out = (float*)d_out;

    static bool cfg = false;
    if (!cfg) {
        cudaFuncSetAttribute(mamba_all_k,
                             cudaFuncAttributeMaxDynamicSharedMemorySize,
                             (int)sizeof(SmemU));
        cfg = true;
    }
    mamba_all_k<<<NBLK, NTHR, sizeof(SmemU)>>>(x, W_in, conv_w, conv_b, W_xp,
                                               W_dt, b_dt, A_log, D_skip,
                                               W_out, rms_w, out);
}

// round 11
// speedup vs baseline: 1.1720x; 1.1720x over previous
#include <cuda_runtime.h>
#include <math.h>

#define L      2304
#define DM     128
#define DI     256
#define DS     16
#define DTR    8
#define NPROJ  40   // DTR + 2*DS
#define NDEPTH 8
#define CHK    16
#define NC     (L/CHK)   // 144
#define NSEQ   (DI*DS)   // 4096
#define SEQT   32

typedef unsigned long long u64;

__device__ __forceinline__ u64 pack2(float lo, float hi) {
    u64 r;
    asm("mov.b64 %0, {%1, %2};" : "=l"(r)
        : "r"(__float_as_uint(lo)), "r"(__float_as_uint(hi)));
    return r;
}
__device__ __forceinline__ u64 fma2(u64 a, u64 b, u64 c) {
    u64 d;
    asm("fma.rn.f32x2 %0, %1, %2, %3;" : "=l"(d) : "l"(a), "l"(b), "l"(c));
    return d;
}
__device__ __forceinline__ void unpack2(u64 v, float& lo, float& hi) {
    unsigned a, b;
    asm("mov.b64 {%0, %1}, %2;" : "=r"(a), "=r"(b) : "l"(v));
    lo = __uint_as_float(a); hi = __uint_as_float(b);
}

// ---------------- scratch (device globals; no allocations) ----------------
__device__ float g_seq[L*DM];
__device__ float g_xz [L*2*DI];
__device__ float g_xc [L*DI];
__device__ float g_dbl[L*NPROJ];
__device__ float g_dt [L*DI];
__device__ float g_chA[NC*NSEQ];   // [chunk][s*DI + d]
__device__ float g_chB[NC*NSEQ];
__device__ float g_h0 [NC*NSEQ];

// ======= in-proj GEMM: xz[L,512] = A[L,128] @ Wi[128,512] =======
// BM=64, BN=128, BK=16; 128 threads, 8x8 per thread via packed f32x2 FMA.
// transA=1: A is x[c,l] (layer 0) read transposed.
__global__ void __launch_bounds__(128) gemm_in_k(const float* __restrict__ A,
                                                 const float* __restrict__ B,
                                                 float* __restrict__ C,
                                                 int transA) {
    __shared__ float As[16][68];
    __shared__ float Bs[16][128];
    int t = threadIdx.x;
    int tr = t >> 4, tc = t & 15;
    int row0 = blockIdx.y * 64, col0 = blockIdx.x * 128;
    u64 acc[8][4];
    #pragma unroll
    for (int i = 0; i < 8; i++)
        #pragma unroll
        for (int j = 0; j < 4; j++) acc[i][j] = 0ull;

    for (int k0 = 0; k0 < DM; k0 += 16) {
        if (transA) {
            // A = x[c=DM][l=L]; As[k][m] = x[k0+k][row0+m]
            #pragma unroll
            for (int i = 0; i < 2; i++) {
                int li = t + i * 128;          // 256 quads: 16 k x 16 m4
                int k = li >> 4, m4 = li & 15;
                float4 v = *(const float4*)&A[(k0 + k) * L + row0 + m4 * 4];
                *(float4*)&As[k][m4 * 4] = v;
            }
        } else {
            #pragma unroll
            for (int i = 0; i < 2; i++) {
                int li = t + i * 128;
                int m = li >> 2, kq = li & 3;
                float4 v = *(const float4*)&A[(row0 + m) * DM + k0 + kq * 4];
                As[kq*4+0][m] = v.x; As[kq*4+1][m] = v.y;
                As[kq*4+2][m] = v.z; As[kq*4+3][m] = v.w;
            }
        }
        #pragma unroll
        for (int i = 0; i < 4; i++) {
            int li = t + i * 128;
            int k = li >> 5, c4 = li & 31;
            *(float4*)&Bs[k][c4 * 4] = *(const float4*)&B[(k0 + k) * 512 + col0 + c4 * 4];
        }
        __syncthreads();
        #pragma unroll
        for (int k = 0; k < 16; k++) {
            float a[8];
            *(float4*)&a[0] = *(float4*)&As[k][tr * 8];
            *(float4*)&a[4] = *(float4*)&As[k][tr * 8 + 4];
            float4 b0 = *(float4*)&Bs[k][tc * 8];
            float4 b1 = *(float4*)&Bs[k][tc * 8 + 4];
            u64 bb[4] = {pack2(b0.x, b0.y), pack2(b0.z, b0.w),
                         pack2(b1.x, b1.y), pack2(b1.z, b1.w)};
            #pragma unroll
            for (int i = 0; i < 8; i++) {
                u64 aa = pack2(a[i], a[i]);
                #pragma unroll
                for (int j = 0; j < 4; j++)
                    acc[i][j] = fma2(aa, bb[j], acc[i][j]);
            }
        }
        __syncthreads();
    }
    #pragma unroll
    for (int i = 0; i < 8; i++) {
        int r = row0 + tr * 8 + i;
        float4 v0, v1;
        unpack2(acc[i][0], v0.x, v0.y); unpack2(acc[i][1], v0.z, v0.w);
        unpack2(acc[i][2], v1.x, v1.y); unpack2(acc[i][3], v1.z, v1.w);
        *(float4*)&C[r * 512 + col0 + tc * 8]     = v0;
        *(float4*)&C[r * 512 + col0 + tc * 8 + 4] = v1;
    }
}

// ======= fused: conv+SiLU -> xproj -> dt(softplus) -> scan pass 1 =======
__global__ void __launch_bounds__(256) fused_mid_k(
    const float* __restrict__ cw, const float* __restrict__ cb,
    const float* __restrict__ Wx, const float* __restrict__ Wdt,
    const float* __restrict__ bdt, const float* __restrict__ Alog)
{
    __shared__ float xc_s[CHK * 257];
    __shared__ float Wx_s[128 * 48];
    __shared__ float dbl_s[CHK * NPROJ];
    int t  = threadIdx.x;
    int l0 = blockIdx.x * CHK;

    float xcr[CHK], dtr[CHK];

    // ---- conv + SiLU: batched loads then compute ----
    {
        int d = t;
        float v[CHK + 3];
        #pragma unroll
        for (int i = 0; i < CHK + 3; i++) {
            int l = l0 + i - 3;
            v[i] = (l >= 0) ? g_xz[l*512 + d] : 0.f;
        }
        float c0 = cw[d*4+0], c1 = cw[d*4+1], c2 = cw[d*4+2], c3 = cw[d*4+3];
        float bb = cb[d];
        #pragma unroll
        for (int r = 0; r < CHK; r++) {
            float acc = bb + v[r]*c0 + v[r+1]*c1 + v[r+2]*c2 + v[r+3]*c3;
            acc = acc / (1.f + __expf(-acc));
            xcr[r] = acc;
            xc_s[r*257 + d] = acc;
            g_xc[(l0+r)*DI + d] = acc;
        }
    }

    // ---- xproj: dbl[16,40] = xc[16,256] @ Wx[256,40] ----
    int row = t & 15, g = t >> 4;
    int c0i = g * 3;
    float a0 = 0.f, a1 = 0.f, a2 = 0.f;
    for (int p = 0; p < 2; p++) {
        __syncthreads();
        for (int i = t; i < 128 * NPROJ; i += 256) {
            int k = i / NPROJ, c = i % NPROJ;
            Wx_s[k*48 + c] = Wx[(p*128 + k) * NPROJ + c];
        }
        __syncthreads();
        const float* xr = xc_s + row*257 + p*128;
        #pragma unroll 4
        for (int k = 0; k < 128; k++) {
            float xv = xr[k];
            a0 += xv * Wx_s[k*48 + c0i];
            a1 += xv * Wx_s[k*48 + c0i + 1];
            a2 += xv * Wx_s[k*48 + c0i + 2];
        }
    }
    if (c0i     < NPROJ) { dbl_s[row*NPROJ + c0i]     = a0; g_dbl[(l0+row)*NPROJ + c0i]     = a0; }
    if (c0i + 1 < NPROJ) { dbl_s[row*NPROJ + c0i + 1] = a1; g_dbl[(l0+row)*NPROJ + c0i + 1] = a1; }
    if (c0i + 2 < NPROJ) { dbl_s[row*NPROJ + c0i + 2] = a2; g_dbl[(l0+row)*NPROJ + c0i + 2] = a2; }
    __syncthreads();

    // ---- dt = softplus ----
    {
        int d = t;
        float w[DTR];
        #pragma unroll
        for (int k = 0; k < DTR; k++) w[k] = Wdt[k*DI + d];
        float bb = bdt[d];
        #pragma unroll
        for (int r = 0; r < CHK; r++) {
            float acc = bb;
            #pragma unroll
            for (int k = 0; k < DTR; k++) acc += dbl_s[r*NPROJ + k] * w[k];
            float sp = (acc > 20.f) ? acc : log1pf(__expf(acc));
            dtr[r] = sp;
            g_dt[(l0+r)*DI + d] = sp;
        }
    }

    // ---- scan pass 1 ----
    {
        int d = t;
        float Arow[DS], a[DS], b[DS];
        #pragma unroll
        for (int s = 0; s < DS; s++) {
            Arow[s] = -__expf(Alog[d*DS + s]);
            a[s] = 1.f; b[s] = 0.f;
        }
        #pragma unroll 4
        for (int r = 0; r < CHK; r++) {
            float dt = dtr[r], dtxc = dt * xcr[r];
            #pragma unroll
            for (int s = 0; s < DS; s++) {
                float dA = __expf(dt * Arow[s]);
                b[s] = dA * b[s] + dtxc * dbl_s[r*NPROJ + DTR + s];
                a[s] *= dA;
            }
        }
        int base = blockIdx.x * NSEQ + d;
        #pragma unroll
        for (int s = 0; s < DS; s++) {
            g_chA[base + s*DI] = a[s];
            g_chB[base + s*DI] = b[s];
        }
    }
}

// ======= scan pass 2: round-parallel Kogge-Stone, batched loads =======
__global__ void __launch_bounds__(512) scan2_k() {
    __shared__ float A_s[NC][SEQT + 1];
    __shared__ float B_s[NC][SEQT + 1];
    int t = threadIdx.x;
    int w = t >> 5, lane = t & 31;
    int seq0 = blockIdx.x * SEQT;

    {
        float la[9], lb[9];
        #pragma unroll
        for (int i = 0; i < 9; i++) {
            int c = w + i * 16;
            la[i] = g_chA[c * NSEQ + seq0 + lane];
            lb[i] = g_chB[c * NSEQ + seq0 + lane];
        }
        #pragma unroll
        for (int i = 0; i < 9; i++) {
            int c = w + i * 16;
            A_s[c][lane] = la[i];
            B_s[c][lane] = lb[i];
        }
    }
    __syncthreads();

    #pragma unroll
    for (int q = 0; q < 2; q++) {
        int col = w * 2 + q;
        float ra[5], rb[5];
        #pragma unroll
        for (int k = 0; k < 5; k++) {
            int c = k * 32 + lane;
            if (c < NC) { ra[k] = A_s[c][col]; rb[k] = B_s[c][col]; }
            else        { ra[k] = 1.f;         rb[k] = 0.f; }
        }
        #pragma unroll
        for (int off = 1; off < 32; off <<= 1) {
            float pa[5], pb[5];
            #pragma unroll
            for (int k = 0; k < 5; k++) {
                pa[k] = __shfl_up_sync(0xffffffffu, ra[k], off);
                pb[k] = __shfl_up_sync(0xffffffffu, rb[k], off);
            }
            #pragma unroll
            for (int k = 0; k < 5; k++)
                if (lane >= off) { rb[k] = ra[k] * pb[k] + rb[k]; ra[k] *= pa[k]; }
        }
        float ea[5], eb[5];
        #pragma unroll
        for (int k = 0; k < 5; k++) {
            ea[k] = __shfl_up_sync(0xffffffffu, ra[k], 1);
            eb[k] = __shfl_up_sync(0xffffffffu, rb[k], 1);
            if (lane == 0) { ea[k] = 1.f; eb[k] = 0.f; }
        }
        float H = 0.f;
        #pragma unroll
        for (int k = 0; k < 5; k++) {
            int c = k * 32 + lane;
            float h0 = ea[k] * H + eb[k];
            if (c < NC) A_s[c][col] = h0;
            float ta = __shfl_sync(0xffffffffu, ra[k], 31);
            float tb = __shfl_sync(0xffffffffu, rb[k], 31);
            H = ta * H + tb;
        }
    }
    __syncthreads();

    #pragma unroll
    for (int i = 0; i < 9; i++) {
        int c = w + i * 16;
        g_h0[c * NSEQ + seq0 + lane] = A_s[c][lane];
    }
}

// ======= fused: scan pass 3 + gate -> out-proj GEMM -> RMSNorm =======
// outp != nullptr (layer 7): write transposed out[c, l] instead of g_seq.
__global__ void __launch_bounds__(256) fused_out_k(
    const float* __restrict__ Alog, const float* __restrict__ Dp,
    const float* __restrict__ Wo, const float* __restrict__ rw,
    float* __restrict__ outp)
{
    __shared__ float y_s[CHK * DI];
    __shared__ float Wo_s[32 * DM];
    __shared__ float Bs_s[CHK][DS];
    __shared__ float Cs_s[CHK][DS];
    int t  = threadIdx.x;
    int l0 = blockIdx.x * CHK;

    {
        int r = t >> 4, s = t & 15;
        int base = (l0 + r) * NPROJ + DTR;
        Bs_s[r][s] = g_dbl[base + s];
        Cs_s[r][s] = g_dbl[base + DS + s];
    }

    // ---- phase A: scan with init state, C-contract, D-skip, z-gate ----
    {
        int d = t;
        float dtv[CHK], xcv[CHK], zv[CHK], h[DS], Arow[DS];
        #pragma unroll
        for (int r = 0; r < CHK; r++) {
            int l = l0 + r;
            dtv[r] = g_dt[l*DI + d];
            xcv[r] = g_xc[l*DI + d];
            zv[r]  = g_xz[l*512 + DI + d];
        }
        int hb = blockIdx.x * NSEQ + d;
        #pragma unroll
        for (int s = 0; s < DS; s++) {
            Arow[s] = -__expf(Alog[d*DS + s]);
            h[s] = g_h0[hb + s*DI];
        }
        float Dd = Dp[d];
        __syncthreads();   // Bs_s/Cs_s ready
        #pragma unroll 4
        for (int r = 0; r < CHK; r++) {
            float dt = dtv[r], xc = xcv[r];
            float dtxc = dt * xc;
            float y = Dd * xc;
            #pragma unroll
            for (int s = 0; s < DS; s++) {
                float dA = __expf(dt * Arow[s]);
                h[s] = dA * h[s] + dtxc * Bs_s[r][s];
                y += h[s] * Cs_s[r][s];
            }
            float z = zv[r];
            y *= z / (1.f + __expf(-z));
            y_s[r*DI + d] = y;
        }
    }

    // ---- phase B: out[16,128] = y[16,256] @ Wo[256,128] + RMSNorm (f32x2) ----
    int w = t >> 5, lane = t & 31;
    int r0 = 2*w, r1 = 2*w + 1;
    int cb = lane * 4;
    u64 acc0[2] = {0ull, 0ull}, acc1[2] = {0ull, 0ull};
    for (int k0 = 0; k0 < DI; k0 += 32) {
        __syncthreads();
        #pragma unroll
        for (int i = 0; i < 4; i++) {
            int idx = t + 256*i;
            int kk = idx >> 5, c4 = idx & 31;
            ((float4*)Wo_s)[kk*32 + c4] = ((const float4*)(Wo + (k0+kk)*DM))[c4];
        }
        __syncthreads();
        #pragma unroll
        for (int kk = 0; kk < 32; kk += 4) {
            float4 y0 = *(const float4*)&y_s[r0*DI + k0 + kk];
            float4 y1 = *(const float4*)&y_s[r1*DI + k0 + kk];
            float ya0[4] = {y0.x, y0.y, y0.z, y0.w};
            float ya1[4] = {y1.x, y1.y, y1.z, y1.w};
            #pragma unroll
            for (int i = 0; i < 4; i++) {
                float4 wv = *(const float4*)&Wo_s[(kk+i)*DM + cb];
                u64 w01 = pack2(wv.x, wv.y), w23 = pack2(wv.z, wv.w);
                u64 a0p = pack2(ya0[i], ya0[i]);
                u64 a1p = pack2(ya1[i], ya1[i]);
                acc0[0] = fma2(a0p, w01, acc0[0]);
                acc0[1] = fma2(a0p, w23, acc0[1]);
                acc1[0] = fma2(a1p, w01, acc1[0]);
                acc1[1] = fma2(a1p, w23, acc1[1]);
            }
        }
    }
    float o0v[4], o1v[4];
    unpack2(acc0[0], o0v[0], o0v[1]); unpack2(acc0[1], o0v[2], o0v[3]);
    unpack2(acc1[0], o1v[0], o1v[1]); unpack2(acc1[1], o1v[2], o1v[3]);
    float ss0 = o0v[0]*o0v[0] + o0v[1]*o0v[1] + o0v[2]*o0v[2] + o0v[3]*o0v[3];
    float ss1 = o1v[0]*o1v[0] + o1v[1]*o1v[1] + o1v[2]*o1v[2] + o1v[3]*o1v[3];
    #pragma unroll
    for (int o = 16; o > 0; o >>= 1) {
        ss0 += __shfl_xor_sync(0xffffffffu, ss0, o);
        ss1 += __shfl_xor_sync(0xffffffffu, ss1, o);
    }
    float sc0 = rsqrtf(ss0 * (1.f/DM) + 1e-5f);
    float sc1 = rsqrtf(ss1 * (1.f/DM) + 1e-5f);
    float4 rwv = *(const float4*)&rw[cb];
    float rws[4] = {rwv.x, rwv.y, rwv.z, rwv.w};
    if (outp) {
        #pragma unroll
        for (int j = 0; j < 4; j++) {
            outp[(cb + j) * L + l0 + r0] = o0v[j] * sc0 * rws[j];
            outp[(cb + j) * L + l0 + r1] = o1v[j] * sc1 * rws[j];
        }
    } else {
        float4 o0, o1;
        o0.x = o0v[0]*sc0*rws[0]; o0.y = o0v[1]*sc0*rws[1];
        o0.z = o0v[2]*sc0*rws[2]; o0.w = o0v[3]*sc0*rws[3];
        o1.x = o1v[0]*sc1*rws[0]; o1.y = o1v[1]*sc1*rws[1];
        o1.z = o1v[2]*sc1*rws[2]; o1.w = o1v[3]*sc1*rws[3];
        *(float4*)&g_seq[(l0 + r0)*DM + cb] = o0;
        *(float4*)&g_seq[(l0 + r1)*DM + cb] = o1;
    }
}

// ---------------- launch ----------------
extern "C" void kernel_launch(void* const* d_in, const int* in_sizes, int n_in,
                              void* d_out, int out_size) {
    const float* x      = (const float*)d_in[0];
    const float* W_in   = (const float*)d_in[1];
    const float* conv_w = (const float*)d_in[2];
    const float* conv_b = (const float*)d_in[3];
    const float* W_xp   = (const float*)d_in[4];
    const float* W_dt   = (const float*)d_in[5];
    const float* b_dt   = (const float*)d_in[6];
    const float* A_log  = (const float*)d_in[7];
    const float* D_skip = (const float*)d_in[8];
    const float* W_out  = (const float*)d_in[9];
    const float* rms_w  = (const float*)d_in[10];
    float* out = (float*)d_out;

    float *p_seq, *p_xz;
    cudaGetSymbolAddress((void**)&p_seq, g_seq);
    cudaGetSymbolAddress((void**)&p_xz,  g_xz);

    for (int l = 0; l < NDEPTH; l++) {
        const float* Wi  = W_in   + (size_t)l * DM * 2 * DI;
        const float* cw  = conv_w + (size_t)l * DI * 4;
        const float* cb  = conv_b + (size_t)l * DI;
        const float* Wx  = W_xp   + (size_t)l * DI * NPROJ;
        const float* Wd  = W_dt   + (size_t)l * DTR * DI;
        const float* bd  = b_dt   + (size_t)l * DI;
        const float* Al  = A_log  + (size_t)l * DI * DS;
        const float* Dpp = D_skip + (size_t)l * DI;
        const float* Wo  = W_out  + (size_t)l * DI * DM;
        const float* rw  = rms_w  + (size_t)l * DM;

        gemm_in_k<<<dim3(4, 36), 128>>>(l == 0 ? x : p_seq, Wi, p_xz, l == 0 ? 1 : 0);
        fused_mid_k<<<NC, 256>>>(cw, cb, Wx, Wd, bd, Al);
        scan2_k<<<NSEQ / SEQT, 512>>>();
        fused_out_k<<<NC, 256>>>(Al, Dpp, Wo, rw, (l == NDEPTH - 1) ? out : nullptr);
    }
}